// round 17
// baseline (speedup 1.0000x reference)
#include <cuda_runtime.h>
#include <cuda_fp16.h>
#include <cstdint>
#include <math.h>
#include <cub/device/device_scan.cuh>

// Problem-fixed sizes (from setup_inputs): N=300000, D=64, E=1000000, R=100000
#define DD 64
static const int    N_MAX = 300032;
static const int    M_MAX = 1200000;
static const size_t TEMP_BYTES = 4u << 20;

// Scratch (device globals — allocation-free per harness rules)
__device__ __align__(16) __half2 g_A[(size_t)N_MAX * 32];   // [N][64] fp16 (b1 folded)
__device__ __align__(16) __half2 g_B[(size_t)N_MAX * 32];
__device__ int            g_cnt [N_MAX];             // per-row entry count
__device__ int            g_offs[N_MAX + 1];         // exclusive prefix -> cursor
__device__ __align__(16) uint4 g_ent[M_MAX];         // packed (row, col, valbits, 0)
__device__ unsigned char  g_temp[TEMP_BYTES];        // CUB scan temp

// ---------------------------------------------------------------------------
// L2 eviction-priority via cache-hint policy.
// ---------------------------------------------------------------------------
__device__ __forceinline__ unsigned long long mk_evict_last_policy() {
    unsigned long long pol;
    asm("createpolicy.fractional.L2::evict_last.b64 %0, 1.0;" : "=l"(pol));
    return pol;
}
__device__ __forceinline__ uint4 ldg_el(const uint4* p, unsigned long long pol) {
    uint4 v;
    asm volatile("ld.global.nc.L2::cache_hint.v4.u32 {%0,%1,%2,%3}, [%4], %5;"
                 : "=r"(v.x), "=r"(v.y), "=r"(v.z), "=r"(v.w)
                 : "l"(p), "l"(pol));
    return v;
}
__device__ __forceinline__ void stg_el(uint4* p, uint4 v, unsigned long long pol) {
    asm volatile("st.global.L2::cache_hint.v4.u32 [%0], {%1,%2,%3,%4}, %5;"
                 :: "l"(p), "r"(v.x), "r"(v.y), "r"(v.z), "r"(v.w), "l"(pol)
                 : "memory");
}

// ---------------------------------------------------------------------------
// Kernel 1: fp16 tensor-core node-factored MLP partials, double-buffered.
// NEW: warp = (table, col-half). 32 cols/warp -> 32 weight regs, 16 acc regs,
// 16-row tiles -> ~110 regs -> 4 blocks/SM (512 thr) for better DRAM overlap.
// Cross-warp staged epilogue writes full 128B rows with evict_last policy.
// ---------------------------------------------------------------------------
#define PITCH2 36   // half2 pitch: conflict-free patterns throughout
#define TROWS  16

__global__ void __launch_bounds__(128, 4)
precompute_mma(const float* __restrict__ emb,
               const float* __restrict__ W1,
               const float* __restrict__ b1,
               int N, int n_tiles) {
    __shared__ __align__(16) __half2 sE[2][TROWS * PITCH2];
    __shared__ __align__(16) __half2 sStage[2][TROWS * PITCH2];  // per table

    const int tid  = threadIdx.x;
    const int warp = tid >> 5;     // 0..3
    const int lane = tid & 31;
    const int gid  = lane >> 2;    // 0..7
    const int tig  = lane & 3;     // 0..3
    const int T    = warp & 1;     // table: 0 -> g_A, 1 -> g_B
    const int H    = warp >> 1;    // column half: 0 or 1

    const unsigned long long pol = mk_evict_last_policy();

    // Weights: cols c = H*32 + nt*8 + gid (nt 0..3) of table T
    unsigned bf[4][4][2];
    float2   b1v[4];
#pragma unroll
    for (int nt = 0; nt < 4; ++nt) {
        int c = H * 32 + nt * 8 + gid;
        const float* wrow = W1 + (size_t)c * 128 + (T ? 64 : 0);
#pragma unroll
        for (int kt = 0; kt < 4; ++kt) {
            __half2 lo = __floats2half2_rn(__ldg(wrow + kt * 16 + 2 * tig),
                                           __ldg(wrow + kt * 16 + 2 * tig + 1));
            __half2 hi = __floats2half2_rn(__ldg(wrow + kt * 16 + 2 * tig + 8),
                                           __ldg(wrow + kt * 16 + 2 * tig + 9));
            bf[kt][nt][0] = *(unsigned*)&lo;
            bf[kt][nt][1] = *(unsigned*)&hi;
        }
        b1v[nt] = T ? make_float2(0.f, 0.f)
                    : __ldg((const float2*)b1 + H * 16 + nt * 4 + tig);
    }

    const int G = gridDim.x;
    int t = blockIdx.x;

    // prologue: load tile t into buffer 0 (16 rows x 32 half2)
    const int lni = tid >> 5;          // row 0..3 (+4 per j)
    const int lh  = tid & 31;          // half2 col
    float2 r[4];
#pragma unroll
    for (int j = 0; j < 4; ++j) {
        int n = t * TROWS + j * 4 + lni;
        r[j] = (t < n_tiles && n < N)
                   ? __ldg((const float2*)(emb + (size_t)n * DD) + lh)
                   : make_float2(0.f, 0.f);
    }
#pragma unroll
    for (int j = 0; j < 4; ++j)
        sE[0][(j * 4 + lni) * PITCH2 + lh] = __floats2half2_rn(r[j].x, r[j].y);
    __syncthreads();

    int buf = 0;
    for (; t < n_tiles; t += G) {
        const int tn = t + G;
        if (tn < n_tiles) {
#pragma unroll
            for (int j = 0; j < 4; ++j) {
                int n = tn * TROWS + j * 4 + lni;
                r[j] = (n < N)
                           ? __ldg((const float2*)(emb + (size_t)n * DD) + lh)
                           : make_float2(0.f, 0.f);
            }
        }

        const int n0 = t * TROWS;
        const __half2* p0 = &sE[buf][gid * PITCH2];
        const __half2* p1 = &sE[buf][(gid + 8) * PITCH2];

        float acc[4][4];
#pragma unroll
        for (int nt = 0; nt < 4; ++nt)
#pragma unroll
            for (int c = 0; c < 4; ++c) acc[nt][c] = 0.f;

#pragma unroll
        for (int kt = 0; kt < 4; ++kt) {
            unsigned a0 = *(const unsigned*)&p0[kt * 8 + tig];
            unsigned a1 = *(const unsigned*)&p1[kt * 8 + tig];
            unsigned a2 = *(const unsigned*)&p0[kt * 8 + tig + 4];
            unsigned a3 = *(const unsigned*)&p1[kt * 8 + tig + 4];
#pragma unroll
            for (int nt = 0; nt < 4; ++nt) {
                asm volatile(
                    "mma.sync.aligned.m16n8k16.row.col.f32.f16.f16.f32 "
                    "{%0,%1,%2,%3}, {%4,%5,%6,%7}, {%8,%9}, {%0,%1,%2,%3};"
                    : "+f"(acc[nt][0]), "+f"(acc[nt][1]),
                      "+f"(acc[nt][2]), "+f"(acc[nt][3])
                    : "r"(a0), "r"(a1), "r"(a2), "r"(a3),
                      "r"(bf[kt][nt][0]), "r"(bf[kt][nt][1]));
            }
        }

        // Stage: table T, rows gid/gid+8, half2 col H*16 + nt*4 + tig
        __half2* st = &sStage[T][0];
#pragma unroll
        for (int nt = 0; nt < 4; ++nt) {
            float2 bb = b1v[nt];
            st[gid * PITCH2 + H * 16 + nt * 4 + tig] =
                __floats2half2_rn(acc[nt][0] + bb.x, acc[nt][1] + bb.y);
            st[(gid + 8) * PITCH2 + H * 16 + nt * 4 + tig] =
                __floats2half2_rn(acc[nt][2] + bb.x, acc[nt][3] + bb.y);
        }
        __syncthreads();   // stage complete (cross-warp)

        // Epilogue: warp w writes table w&1, rows (w>>1)*8 .. +8 (full 128B rows)
        {
            __half2* tabw = (T == 0) ? g_A : g_B;
            const char* stw = (const char*)&sStage[T][0];
            int rowbase = H * 8;
#pragma unroll
            for (int i = 0; i < 2; ++i) {
                int rr = rowbase + i * 4 + (lane >> 3);
                int cc = lane & 7;
                int n  = n0 + rr;
                if (n < N) {
                    uint4 v = *(const uint4*)(stw + rr * (PITCH2 * 4) + cc * 16);
                    stg_el((uint4*)((char*)(tabw + (size_t)n * 32) + cc * 16), v, pol);
                }
            }
        }

        // store next tile into the other buffer
        if (tn < n_tiles) {
#pragma unroll
            for (int j = 0; j < 4; ++j)
                sE[buf ^ 1][(j * 4 + lni) * PITCH2 + lh] =
                    __floats2half2_rn(r[j].x, r[j].y);
        }
        __syncthreads();   // sE[buf^1] ready; sStage reusable
        buf ^= 1;
    }
}

// ---------------------------------------------------------------------------
// Kernel 2: row histogram over all (edge + random) entries.
// ---------------------------------------------------------------------------
__global__ void hist_kernel(const int* __restrict__ ei,
                            const int* __restrict__ ri, int E, int R) {
    int i = blockIdx.x * blockDim.x + threadIdx.x;
    if (i < E)          atomicAdd(&g_cnt[ei[i]], 1);
    else if (i < E + R) atomicAdd(&g_cnt[ri[i - E]], 1);
}

// ---------------------------------------------------------------------------
// Register-only half2-bits -> float2 (no pointer reinterpretation).
// ---------------------------------------------------------------------------
__device__ __forceinline__ float2 u2f2(unsigned u) {
    __half2_raw hr;
    hr.x = (unsigned short)(u & 0xFFFFu);
    hr.y = (unsigned short)(u >> 16);
    return __half22float2(__half2(hr));
}

__device__ __forceinline__ float dot_u4(uint4 a, uint4 b, const float2* w2v) {
    float acc = 0.f;
    float2 av, bv;
    av = u2f2(a.x); bv = u2f2(b.x);
    acc += fmaxf(av.x + bv.x, 0.f) * w2v[0].x + fmaxf(av.y + bv.y, 0.f) * w2v[0].y;
    av = u2f2(a.y); bv = u2f2(b.y);
    acc += fmaxf(av.x + bv.x, 0.f) * w2v[1].x + fmaxf(av.y + bv.y, 0.f) * w2v[1].y;
    av = u2f2(a.z); bv = u2f2(b.z);
    acc += fmaxf(av.x + bv.x, 0.f) * w2v[2].x + fmaxf(av.y + bv.y, 0.f) * w2v[2].y;
    av = u2f2(a.w); bv = u2f2(b.w);
    acc += fmaxf(av.x + bv.x, 0.f) * w2v[3].x + fmaxf(av.y + bv.y, 0.f) * w2v[3].y;
    return acc;
}

// ---------------------------------------------------------------------------
// Kernel 3: edges + random entries in one launch; packed uint4 scatter.
// (unchanged from R15 winner)
// ---------------------------------------------------------------------------
__global__ void edge_rand_kernel(const int* __restrict__ ei,
                                 const float* __restrict__ W2,
                                 const float* __restrict__ b2,
                                 const float* __restrict__ eps_u,
                                 const float* __restrict__ rb_u,
                                 const int* __restrict__ ri,
                                 int E, int R, int EB) {
    __shared__ float s_logit[256];
    __shared__ int   s_src[256];
    __shared__ int   s_dst[256];

    if (blockIdx.x >= EB) {
        int r = (blockIdx.x - EB) * 256 + threadIdx.x;
        if (r < R) {
            int row = __ldg(ri + r);
            int col = __ldg(ri + R + r);
            int pos = atomicAdd(&g_offs[row], 1);
            g_ent[pos] = make_uint4((unsigned)row, (unsigned)col,
                                    __float_as_uint(0.05f), 0u);
        }
        return;
    }

    const int tid  = threadIdx.x;
    const int sub  = tid & 7;
    const int le   = tid >> 3;          // 0..31
    const int base = blockIdx.x * 256;

    const uint4* At = (const uint4*)g_A;   // row = 8 uint4
    const uint4* Bt = (const uint4*)g_B;
    const unsigned long long pol = mk_evict_last_policy();

    float2 w2v[4];
#pragma unroll
    for (int q = 0; q < 4; ++q)
        w2v[q] = __ldg((const float2*)W2 + sub * 4 + q);

    // batch all index loads (coalesced, L2-hot); clamp OOB lanes to row 0
    int srcs[8], dsts[8];
#pragma unroll
    for (int i = 0; i < 8; ++i) {
        int e = base + i * 32 + le;
        bool ok = (e < E);
        srcs[i] = ok ? __ldg(ei + e)     : 0;
        dsts[i] = ok ? __ldg(ei + E + e) : 0;
        if (sub == 0) {
            s_src[i * 32 + le] = srcs[i];
            s_dst[i * 32 + le] = dsts[i];
        }
    }

    float p[8];
#pragma unroll
    for (int h = 0; h < 2; ++h) {
        const int i0 = h * 4;
        uint4 A0 = ldg_el(At + (size_t)srcs[i0 + 0] * 8 + sub, pol);
        uint4 B0 = ldg_el(Bt + (size_t)dsts[i0 + 0] * 8 + sub, pol);
        uint4 A1 = ldg_el(At + (size_t)srcs[i0 + 1] * 8 + sub, pol);
        uint4 B1 = ldg_el(Bt + (size_t)dsts[i0 + 1] * 8 + sub, pol);
        uint4 A2 = ldg_el(At + (size_t)srcs[i0 + 2] * 8 + sub, pol);
        uint4 B2 = ldg_el(Bt + (size_t)dsts[i0 + 2] * 8 + sub, pol);
        uint4 A3 = ldg_el(At + (size_t)srcs[i0 + 3] * 8 + sub, pol);
        uint4 B3 = ldg_el(Bt + (size_t)dsts[i0 + 3] * 8 + sub, pol);
        p[i0 + 0] = dot_u4(A0, B0, w2v);
        p[i0 + 1] = dot_u4(A1, B1, w2v);
        p[i0 + 2] = dot_u4(A2, B2, w2v);
        p[i0 + 3] = dot_u4(A3, B3, w2v);
    }

#pragma unroll
    for (int i = 0; i < 8; ++i) {
        float v = p[i];
        v += __shfl_xor_sync(0xffffffffu, v, 4);
        v += __shfl_xor_sync(0xffffffffu, v, 2);
        v += __shfl_xor_sync(0xffffffffu, v, 1);
        if (sub == 0) s_logit[i * 32 + le] = v;
    }
    __syncthreads();

    int e = base + tid;
    if (e < E) {
        const float LOG2E  = 1.4426950408889634f;
        const float LOG299 = 6.6293566200796095f;   // log2(99)

        int src = s_src[tid];
        int dst = s_dst[tid];
        float logit = s_logit[tid] + __ldg(b2);

        float eu        = __ldg(eps_u + e);
        float eps       = fmaf(-0.9998f, eu, 0.9999f);
        float one_m_eps = fmaf( 0.9998f, eu, 0.0001f);   // exact complement
        float u         = fminf(fmaxf(__ldg(rb_u + e), 1e-7f), 1.0f - 1e-7f);
        float one_m_u   = 1.0f - u;

        float La = __log2f(eps) - __log2f(one_m_eps) + logit * LOG2E;
        float Lc = fminf(fmaxf(La, -LOG299), LOG299);
        float Lz = (Lc + __log2f(u) - __log2f(one_m_u)) * (10.0f / 9.0f);
        float z  = exp2f(Lz);
        float s  = __fdividef(z, 1.0f + z);
        // mask = (s > 0) is always 1 (z > 0), so mat = s
        int pos = atomicAdd(&g_offs[src], 1);
        g_ent[pos] = make_uint4((unsigned)src, (unsigned)dst,
                                __float_as_uint(s), 0u);
    }
}

// ---------------------------------------------------------------------------
// Kernel 4: element-parallel rank/coalesce + output (packed entries).
// out layout: [0..M) rows, [M..2M) cols, [2M..3M) vals (float32)
// ---------------------------------------------------------------------------
__global__ void finalize_kernel(float* __restrict__ out, int M, int vals_only) {
    int i = blockIdx.x * blockDim.x + threadIdx.x;
    if (i >= M) return;

    uint4 me = g_ent[i];
    int      row   = (int)me.x;
    unsigned mycol = me.y;
    float    sum   = __uint_as_float(me.z);

    int end   = g_offs[row];          // segment end (post-scatter cursor)
    int cnt   = g_cnt[row];
    int start = end - cnt;

    int  rank = 0;
    bool head = true;
    for (int j = start; j < end; ++j) {
        if (j == i) continue;
        uint4 ej = g_ent[j];
        unsigned c = ej.y;
        if (c < mycol || (c == mycol && j < i)) ++rank;
        if (c == mycol) {
            if (j < i) head = false;
            sum += __uint_as_float(ej.z);
        }
    }

    int   o  = start + rank;
    float ov = head ? sum : 0.0f;
    if (vals_only) {
        out[o] = ov;
    } else {
        out[o]         = (float)row;
        out[M + o]     = (float)mycol;
        out[2 * M + o] = ov;
    }
}

// ---------------------------------------------------------------------------
extern "C" void kernel_launch(void* const* d_in, const int* in_sizes, int n_in,
                              void* d_out, int out_size) {
    const float* emb   = (const float*)d_in[0];
    const float* W1    = (const float*)d_in[1];
    const float* b1    = (const float*)d_in[2];
    const float* W2    = (const float*)d_in[3];
    const float* b2    = (const float*)d_in[4];
    const int*   ei    = (const int*)  d_in[5];
    const int*   ri    = (const int*)  d_in[6];
    const float* eps_u = (const float*)d_in[7];
    const float* rb_u  = (const float*)d_in[8];

    const int N = in_sizes[0] / DD;
    const int E = in_sizes[5] / 2;
    const int R = in_sizes[6] / 2;
    const int M = E + R;

    void *p_cnt, *p_offs, *p_tmp;
    cudaGetSymbolAddress(&p_cnt,  g_cnt);
    cudaGetSymbolAddress(&p_offs, g_offs);
    cudaGetSymbolAddress(&p_tmp,  g_temp);

    // Aux stream + fork/join events (host objects only; leaked deliberately —
    // destroying them mid-capture would invalidate the capture).
    cudaStream_t s_aux;
    cudaEvent_t  ev_fork, ev_join;
    cudaStreamCreateWithFlags(&s_aux, cudaStreamNonBlocking);
    cudaEventCreateWithFlags(&ev_fork, cudaEventDisableTiming);
    cudaEventCreateWithFlags(&ev_join, cudaEventDisableTiming);

    // ---- fork: index chain (memset -> hist -> scan) on aux stream ----
    cudaEventRecord(ev_fork, (cudaStream_t)0);
    cudaStreamWaitEvent(s_aux, ev_fork, 0);

    cudaMemsetAsync(p_cnt, 0, (size_t)N * sizeof(int), s_aux);
    hist_kernel<<<(E + R + 255) / 256, 256, 0, s_aux>>>(ei, ri, E, R);
    size_t tb = TEMP_BYTES;
    cub::DeviceScan::ExclusiveSum(p_tmp, tb, (const int*)p_cnt, (int*)p_offs,
                                  N, s_aux);
    cudaEventRecord(ev_join, s_aux);

    // ---- main stream: fp16 tensor-core MLP partials (overlaps aux) ----
    int n_tiles = (N + TROWS - 1) / TROWS;
    int grid = 148 * 4;
    if (grid > n_tiles) grid = n_tiles;
    precompute_mma<<<grid, 128>>>(emb, W1, b1, N, n_tiles);

    // ---- join ----
    cudaStreamWaitEvent((cudaStream_t)0, ev_join, 0);

    // ---- edges + random entries, packed scatter into row segments ----
    int EB = (E + 255) / 256;
    int RB = (R + 255) / 256;
    edge_rand_kernel<<<EB + RB, 256>>>(ei, W2, b2, eps_u, rb_u, ri, E, R, EB);

    // ---- element-parallel rank/coalesce + output ----
    int vals_only = (out_size == M) ? 1 : 0;
    finalize_kernel<<<(M + 255) / 256, 256>>>((float*)d_out, M, vals_only);
}